// round 13
// baseline (speedup 1.0000x reference)
#include <cuda_runtime.h>
#include <cuda_fp16.h>
#include <cuda_bf16.h>
#include <cfloat>

#define LEAKF 0.2f
#define SCALE 256.0f
#define UNSCALE (1.0f / 65536.0f)
#define PLANE (128 * 16)            // words per matrix per stage (row = 16 words)
#define PLANEB (PLANE * 4)          // 8192 B
#define STAGEB (2 * PLANEB)         // 16384 B (A + B)
#define SMEM_DYN (2 * STAGEB)       // 32768 B double-buffered

// ---------------- device scratch (no allocation allowed) ----------------
__device__ float g_d[4L * 4096 * 4096];   // 256 MB distance matrices
__device__ float g_cat[16384L * 512];
__device__ float g_qp[16384L * 512];
__device__ float g_x2[16384];
__device__ int   g_idx[16384L * 20];
__device__ float g_local[16384L * 512];
__device__ float g_emb[16384L * 1024];
__device__ float g_part[64L * 1024];
__device__ float g_glob[4L * 1024];
__device__ float g_gh[4L * 256];
__device__ float g_h1[16384L * 256];
__device__ float g_h2[16384L * 256];
__device__ float g_wp[512 * 128];
__device__ unsigned g_ahl[16384L * 512];  // activations: packed fp16 (h0,h1), K16 words/row
__device__ unsigned g_bhl[1024L * 512];   // weights: same layout

__device__ __forceinline__ float lrelu(float v) { return v > 0.f ? v : LEAKF * v; }

__device__ __forceinline__ unsigned f2tf32(float v) {
    unsigned r;
    asm("cvt.rna.tf32.f32 %0, %1;" : "=r"(r) : "f"(v));
    return r;
}

__device__ __forceinline__ void cpasync16(unsigned saddr, const void* g) {
    asm volatile("cp.async.ca.shared.global [%0], [%1], 16;" :: "r"(saddr), "l"(g));
}
__device__ __forceinline__ void cpcommit() { asm volatile("cp.async.commit_group;"); }
template<int N>
__device__ __forceinline__ void cpwait() { asm volatile("cp.async.wait_group %0;" :: "n"(N)); }

// ---------------- fp16 hi/lo pre-decomposition (scaled 2^8), mma-ready layout ------
__global__ void conv_k(const float* __restrict__ src, int ld, int rows, int C,
                       int K16, unsigned* __restrict__ ohl)
{
    int r = blockIdx.x;
    long rowbase = (long)r * K16;
    for (int q = threadIdx.x; q < K16 / 2; q += blockDim.x) {
        int k0 = 2 * q;
        float v0 = (r < rows && k0 < C) ? src[(long)r * ld + k0] * SCALE : 0.f;
        float v1 = (r < rows && k0 + 1 < C) ? src[(long)r * ld + k0 + 1] * SCALE : 0.f;
        __half h0a = __float2half_rn(v0);
        __half h1a = __float2half_rn(v0 - __half2float(h0a));
        __half h0b = __float2half_rn(v1);
        __half h1b = __float2half_rn(v1 - __half2float(h0b));
        unsigned hi = ((unsigned)__half_as_ushort(h0b) << 16) | __half_as_ushort(h0a);
        unsigned lo = ((unsigned)__half_as_ushort(h1b) << 16) | __half_as_ushort(h1a);
        int chunk = q >> 3, c = q & 7;
        int g = c >> 2, p = c & 3;
        long base = rowbase + chunk * 16 + p * 4;
        ohl[base + g] = hi;
        ohl[base + 2 + g] = lo;
    }
}

// ---------------- 128x128 fp16x2 MMA GEMM (m16n8k16), cp.async double-buffered ----
// MODE 0: Y = acc
// MODE 1: Y = leaky(acc*s[n] + b[n])
// MODE 2: Y = x2[m] + x2[n] - 2*acc  (SYM=1: upper-tri tiles, mirrored writes)
// MODE 3: Y = leaky(s[n]*(acc + aux[(m>>12)*auxS + n]) + b[n])
// MODE 4: Y = acc + b[n]
template<int MODE, int SYM>
__global__ __launch_bounds__(256, 2)
void gemm_cp(const unsigned* __restrict__ Ahl, long abs_,
             const unsigned* __restrict__ Bhl, long bbs,
             int lda, int ldb,
             float* __restrict__ Y, int ldy, long ybs,
             int M, int K16, int NO,
             const float* __restrict__ sv, const float* __restrict__ bv,
             const float* __restrict__ aux, int auxS)
{
    extern __shared__ unsigned smd[];
    unsigned sb32 = (unsigned)__cvta_generic_to_shared(smd);

    int z = blockIdx.z;
    const unsigned* Ag = Ahl + (long)z * abs_;
    const unsigned* Bg = Bhl + (long)z * bbs;
    float* Yb = Y + (long)z * ybs;

    int row0, col0;
    if (SYM) {
        int T = (M + 127) >> 7;
        int t = blockIdx.x;
        float ff = (float)(2 * T + 1);
        int bi = (int)((ff - sqrtf(ff * ff - 8.f * (float)t)) * 0.5f);
        while ((bi + 1) * T - ((bi + 1) * bi) / 2 <= t) bi++;
        while (bi * T - (bi * (bi - 1)) / 2 > t) bi--;
        int bj = bi + (t - (bi * T - (bi * (bi - 1)) / 2));
        row0 = bi << 7;
        col0 = bj << 7;
    } else {
        row0 = blockIdx.y * 128;
        col0 = blockIdx.x * 128;
    }

    int tid = threadIdx.x;
    int lane = tid & 31, wid = tid >> 5;
    int wm = wid & 3, wn = wid >> 2;
    int grp = lane >> 2, tig = lane & 3;

    float acc[2][8][4];
#pragma unroll
    for (int h = 0; h < 2; h++)
#pragma unroll
        for (int j = 0; j < 8; j++)
#pragma unroll
            for (int c = 0; c < 4; c++) acc[h][j][c] = 0.f;

    int nch = K16 >> 4;

    auto load_stage = [&](int stage, int ch) {
        unsigned base = sb32 + stage * STAGEB;
#pragma unroll
        for (int v = 0; v < 2; v++) {
            int qlin = tid + v * 256;
            int row = qlin >> 2, q = qlin & 3;
            unsigned soff = (unsigned)(row * 16 + q * 4) * 4u;
            long goa = (long)(row0 + row) * lda + (long)ch * 16 + q * 4;
            long gob = (long)(col0 + row) * ldb + (long)ch * 16 + q * 4;
            cpasync16(base + soff,          Ag + goa);
            cpasync16(base + PLANEB + soff, Bg + gob);
        }
        cpcommit();
    };

    load_stage(0, 0);

    for (int ch = 0; ch < nch; ch++) {
        int cur = ch & 1;
        if (ch + 1 < nch) load_stage(cur ^ 1, ch + 1);
        if (ch + 1 < nch) cpwait<1>(); else cpwait<0>();
        __syncthreads();

        const unsigned* As = smd + cur * 2 * PLANE;
        const unsigned* Bs = As + PLANE;

        unsigned ah[2][4], al[2][4];
#pragma unroll
        for (int h = 0; h < 2; h++) {
            int r0 = wm * 32 + h * 16 + grp;
            uint4 pa0 = *(const uint4*)&As[r0 * 16 + tig * 4];
            uint4 pa1 = *(const uint4*)&As[(r0 + 8) * 16 + tig * 4];
            ah[h][0] = pa0.x; ah[h][1] = pa1.x; ah[h][2] = pa0.y; ah[h][3] = pa1.y;
            al[h][0] = pa0.z; al[h][1] = pa1.z; al[h][2] = pa0.w; al[h][3] = pa1.w;
        }
#pragma unroll
        for (int j = 0; j < 8; j++) {
            int rb = wn * 64 + j * 8 + grp;
            uint4 pb = *(const uint4*)&Bs[rb * 16 + tig * 4];
            unsigned bh0 = pb.x, bh1 = pb.y, bl0 = pb.z, bl1 = pb.w;
#pragma unroll
            for (int h = 0; h < 2; h++) {
                asm volatile(
                    "mma.sync.aligned.m16n8k16.row.col.f32.f16.f16.f32 "
                    "{%0,%1,%2,%3}, {%4,%5,%6,%7}, {%8,%9}, {%0,%1,%2,%3};"
                    : "+f"(acc[h][j][0]), "+f"(acc[h][j][1]),
                      "+f"(acc[h][j][2]), "+f"(acc[h][j][3])
                    : "r"(al[h][0]), "r"(al[h][1]), "r"(al[h][2]), "r"(al[h][3]),
                      "r"(bh0), "r"(bh1));
                asm volatile(
                    "mma.sync.aligned.m16n8k16.row.col.f32.f16.f16.f32 "
                    "{%0,%1,%2,%3}, {%4,%5,%6,%7}, {%8,%9}, {%0,%1,%2,%3};"
                    : "+f"(acc[h][j][0]), "+f"(acc[h][j][1]),
                      "+f"(acc[h][j][2]), "+f"(acc[h][j][3])
                    : "r"(ah[h][0]), "r"(ah[h][1]), "r"(ah[h][2]), "r"(ah[h][3]),
                      "r"(bl0), "r"(bl1));
                asm volatile(
                    "mma.sync.aligned.m16n8k16.row.col.f32.f16.f16.f32 "
                    "{%0,%1,%2,%3}, {%4,%5,%6,%7}, {%8,%9}, {%0,%1,%2,%3};"
                    : "+f"(acc[h][j][0]), "+f"(acc[h][j][1]),
                      "+f"(acc[h][j][2]), "+f"(acc[h][j][3])
                    : "r"(ah[h][0]), "r"(ah[h][1]), "r"(ah[h][2]), "r"(ah[h][3]),
                      "r"(bh0), "r"(bh1));
            }
        }
        __syncthreads();
    }

#pragma unroll
    for (int h = 0; h < 2; h++) {
        int r0 = row0 + wm * 32 + h * 16 + grp;
#pragma unroll
        for (int j = 0; j < 8; j++) {
            int cb = col0 + wn * 64 + j * 8 + 2 * tig;
#pragma unroll
            for (int half = 0; half < 2; half++) {
                int gm = r0 + half * 8;
                if (gm >= M) continue;
#pragma unroll
                for (int cc = 0; cc < 2; cc++) {
                    int gn = cb + cc;
                    if (gn >= NO) continue;
                    float v = acc[h][j][half * 2 + cc] * UNSCALE;
                    if (MODE == 1) v = lrelu(v * sv[gn] + bv[gn]);
                    else if (MODE == 2) {
                        const float* x2 = aux + (long)z * auxS;
                        v = x2[gm] + x2[gn] - 2.f * v;
                    } else if (MODE == 3) {
                        int bb = gm >> 12;
                        v = lrelu(sv[gn] * (v + aux[bb * auxS + gn]) + bv[gn]);
                    } else if (MODE == 4) v = v + bv[gn];
                    Yb[(long)gm * ldy + gn] = v;
                    if (SYM) Yb[(long)gn * ldy + gm] = v;
                }
            }
        }
    }
}

// ---------------- scalar-load 3xTF32 GEMM (tiny 4x256 GEMM only) ------
template<int MODE>
__global__ __launch_bounds__(256, 2)
void gemm_t(const float* __restrict__ X, int ldx,
            const float* __restrict__ W, int ldw,
            float* __restrict__ Y, int ldy,
            int M, int K, int NO)
{
    __shared__ unsigned Ah[128 * 20];
    __shared__ unsigned Bh[128 * 20];
    __shared__ unsigned Al[128 * 20];
    __shared__ unsigned Bl[128 * 20];
    const int SPD = 20;

    int row0 = blockIdx.y * 128;
    int col0 = blockIdx.x * 128;
    int tid = threadIdx.x;
    int lane = tid & 31, wid = tid >> 5;
    int wm = wid & 3, wn = wid >> 2;
    int grp = lane >> 2, tig = lane & 3;

    float acc[2][8][4];
#pragma unroll
    for (int h = 0; h < 2; h++)
#pragma unroll
        for (int j = 0; j < 8; j++)
#pragma unroll
            for (int c = 0; c < 4; c++) acc[h][j][c] = 0.f;

    int nchunks = (K + 15) >> 4;
    for (int ch = 0; ch < nchunks; ch++) {
        int k0 = ch << 4;
#pragma unroll
        for (int i = 0; i < 8; i++) {
            int li = tid * 8 + i;
            int rrow = li >> 4, rcol = li & 15;
            int gk = k0 + rcol;
            int gm = row0 + rrow;
            float va = (gm < M && gk < K) ? X[(long)gm * ldx + gk] : 0.f;
            unsigned vah = f2tf32(va);
            Ah[rrow * SPD + rcol] = vah;
            Al[rrow * SPD + rcol] = f2tf32(va - __uint_as_float(vah));
            int gn = col0 + rrow;
            float vb = (gn < NO && gk < K) ? W[(long)gn * ldw + gk] : 0.f;
            unsigned vbh = f2tf32(vb);
            Bh[rrow * SPD + rcol] = vbh;
            Bl[rrow * SPD + rcol] = f2tf32(vb - __uint_as_float(vbh));
        }
        __syncthreads();
#pragma unroll
        for (int ks = 0; ks < 16; ks += 8) {
            unsigned ah[2][4], al[2][4];
#pragma unroll
            for (int h = 0; h < 2; h++) {
                int mb = wm * 32 + h * 16;
                int i0 = (mb + grp) * SPD + ks + tig;
                int i1 = (mb + grp + 8) * SPD + ks + tig;
                ah[h][0] = Ah[i0]; ah[h][1] = Ah[i1];
                ah[h][2] = Ah[i0 + 4]; ah[h][3] = Ah[i1 + 4];
                al[h][0] = Al[i0]; al[h][1] = Al[i1];
                al[h][2] = Al[i0 + 4]; al[h][3] = Al[i1 + 4];
            }
#pragma unroll
            for (int j = 0; j < 8; j++) {
                int nb = wn * 64 + j * 8;
                int ib = (nb + grp) * SPD + ks + tig;
                unsigned bh0 = Bh[ib], bh1 = Bh[ib + 4];
                unsigned bl0 = Bl[ib], bl1 = Bl[ib + 4];
#pragma unroll
                for (int h = 0; h < 2; h++) {
                    asm volatile(
                        "mma.sync.aligned.m16n8k8.row.col.f32.tf32.tf32.f32 "
                        "{%0,%1,%2,%3}, {%4,%5,%6,%7}, {%8,%9}, {%0,%1,%2,%3};"
                        : "+f"(acc[h][j][0]), "+f"(acc[h][j][1]),
                          "+f"(acc[h][j][2]), "+f"(acc[h][j][3])
                        : "r"(al[h][0]), "r"(al[h][1]), "r"(al[h][2]), "r"(al[h][3]),
                          "r"(bh0), "r"(bh1));
                    asm volatile(
                        "mma.sync.aligned.m16n8k8.row.col.f32.tf32.tf32.f32 "
                        "{%0,%1,%2,%3}, {%4,%5,%6,%7}, {%8,%9}, {%0,%1,%2,%3};"
                        : "+f"(acc[h][j][0]), "+f"(acc[h][j][1]),
                          "+f"(acc[h][j][2]), "+f"(acc[h][j][3])
                        : "r"(ah[h][0]), "r"(ah[h][1]), "r"(ah[h][2]), "r"(ah[h][3]),
                          "r"(bl0), "r"(bl1));
                    asm volatile(
                        "mma.sync.aligned.m16n8k8.row.col.f32.tf32.tf32.f32 "
                        "{%0,%1,%2,%3}, {%4,%5,%6,%7}, {%8,%9}, {%0,%1,%2,%3};"
                        : "+f"(acc[h][j][0]), "+f"(acc[h][j][1]),
                          "+f"(acc[h][j][2]), "+f"(acc[h][j][3])
                        : "r"(ah[h][0]), "r"(ah[h][1]), "r"(ah[h][2]), "r"(ah[h][3]),
                          "r"(bh0), "r"(bh1));
                }
            }
        }
        __syncthreads();
    }
#pragma unroll
    for (int h = 0; h < 2; h++) {
        int r0 = row0 + wm * 32 + h * 16 + grp;
#pragma unroll
        for (int j = 0; j < 8; j++) {
            int cb = col0 + wn * 64 + j * 8 + 2 * tig;
#pragma unroll
            for (int half = 0; half < 2; half++) {
                int gm = r0 + half * 8;
                if (gm >= M) continue;
#pragma unroll
                for (int cc = 0; cc < 2; cc++) {
                    int gn = cb + cc;
                    if (gn >= NO) continue;
                    Y[(long)gm * ldy + gn] = acc[h][j][half * 2 + cc];
                }
            }
        }
    }
}

// ---------------- squared norms (warp per row) ----------------
__global__ void sqnorm_k(const float* __restrict__ X, int ldx, int C, float* __restrict__ x2)
{
    int warp = (blockIdx.x * blockDim.x + threadIdx.x) >> 5;
    int lane = threadIdx.x & 31;
    if (warp >= 16384) return;
    const float* xr = X + (long)warp * ldx;
    float s = 0.f;
    for (int c = lane; c < C; c += 32) { float v = xr[c]; s = fmaf(v, v, s); }
#pragma unroll
    for (int off = 16; off; off >>= 1) s += __shfl_down_sync(0xffffffffu, s, off);
    if (lane == 0) x2[warp] = s;
}

// ---------------- top-20 smallest: normalized-bin radix select, reg-resident ------
// Keys held in registers (16/thread). Per-row normalization (subtract block min,
// shift by range bits) spreads the clustered distance keys uniformly over 2048
// bins -> histogram atomics nearly conflict-free. Binning is monotone in key, so
// the selected set (exact (key,idx) top-20) is identical to previous rounds.
__global__ __launch_bounds__(256) void topk_k(const float* __restrict__ D, int* __restrict__ idx)
{
    __shared__ int hist[2048];
    __shared__ unsigned long long cand[2048];
    __shared__ int wsum[8];
    __shared__ unsigned wmn[8], wmx[8];
    __shared__ int sb, sexcl, socnt, sccnt;
    __shared__ unsigned long long wred[8];
    __shared__ unsigned long long s_last;

    long r = blockIdx.x;
    const float4* drow = (const float4*)(D + r * 4096);
    int* orow = idx + r * 20;
    int tid = threadIdx.x;
    int lane = tid & 31, warp = tid >> 5;

    // load 16 keys into registers
    unsigned key[16];
#pragma unroll
    for (int v = 0; v < 4; v++) {
        float4 d4 = drow[tid + v * 256];
        key[v * 4 + 0] = __float_as_uint(fmaxf(d4.x, 0.f));
        key[v * 4 + 1] = __float_as_uint(fmaxf(d4.y, 0.f));
        key[v * 4 + 2] = __float_as_uint(fmaxf(d4.z, 0.f));
        key[v * 4 + 3] = __float_as_uint(fmaxf(d4.w, 0.f));
    }

    // block min/max + hist zero
    unsigned mn = 0xffffffffu, mx = 0u;
#pragma unroll
    for (int i = 0; i < 16; i++) { mn = min(mn, key[i]); mx = max(mx, key[i]); }
#pragma unroll
    for (int off = 16; off; off >>= 1) {
        mn = min(mn, __shfl_down_sync(0xffffffffu, mn, off));
        mx = max(mx, __shfl_down_sync(0xffffffffu, mx, off));
    }
    if (lane == 0) { wmn[warp] = mn; wmx[warp] = mx; }
#pragma unroll
    for (int i = 0; i < 8; i++) hist[tid + i * 256] = 0;
    if (tid == 0) { socnt = 0; sccnt = 0; s_last = 0ull; }
    __syncthreads();

    unsigned umin = wmn[0], umax = wmx[0];
#pragma unroll
    for (int i = 1; i < 8; i++) { umin = min(umin, wmn[i]); umax = max(umax, wmx[i]); }
    unsigned range = umax - umin;
    int bits = 32 - __clz(range | 1u);
    int shift = bits > 11 ? bits - 11 : 0;

    // histogram (normalized bins)
#pragma unroll
    for (int i = 0; i < 16; i++)
        atomicAdd(&hist[(key[i] - umin) >> shift], 1);
    __syncthreads();

    // block scan over 2048 bins -> boundary bin (excl < 20 <= incl)
    int csum[8];
    int tot = 0;
#pragma unroll
    for (int i = 0; i < 8; i++) { tot += hist[tid * 8 + i]; csum[i] = tot; }
    int sc = tot;
#pragma unroll
    for (int off = 1; off < 32; off <<= 1) {
        int t = __shfl_up_sync(0xffffffffu, sc, off);
        if (lane >= off) sc += t;
    }
    if (lane == 31) wsum[warp] = sc;
    __syncthreads();
    if (tid < 8) {
        int w = wsum[tid];
#pragma unroll
        for (int off = 1; off < 8; off <<= 1) {
            int t = __shfl_up_sync(0xffu, w, off);
            if (tid >= off) w += t;
        }
        wsum[tid] = w;
    }
    __syncthreads();
    int base = sc - tot + (warp ? wsum[warp - 1] : 0);

    if (base < 20 && base + tot >= 20) {
#pragma unroll
        for (int i = 0; i < 8; i++) {
            int incl = base + csum[i];
            int excl = incl - hist[tid * 8 + i];
            if (excl < 20 && incl >= 20) { sb = tid * 8 + i; sexcl = excl; }
        }
    }
    __syncthreads();
    unsigned b = (unsigned)sb;
    int need = 20 - sexcl;

    // emission from registers: winners -> orow, boundary -> cand (packed key|idx)
#pragma unroll
    for (int i = 0; i < 16; i++) {
        unsigned bin = (key[i] - umin) >> shift;
        if (bin < b) {
            int p = atomicAdd(&socnt, 1);
            orow[p] = (tid + (i >> 2) * 256) * 4 + (i & 3);
        } else if (bin == b) {
            int p = atomicAdd(&sccnt, 1);
            if (p < 2048) {
                int j = (tid + (i >> 2) * 256) * 4 + (i & 3);
                cand[p] = ((unsigned long long)key[i] << 32) | (unsigned)j;
            }
        }
    }
    __syncthreads();
    int m = sccnt;
    bool fallback = (m > 2048);
    int obase = socnt;

    // exact finish: unique (key, idx) iterative min
    for (int t = 0; t < need; t++) {
        unsigned long long last = s_last;
        unsigned long long best = ~0ull;
        if (!fallback) {
            for (int c = tid; c < m; c += 256) {
                unsigned long long k2 = cand[c];
                if (k2 > last && k2 < best) best = k2;
            }
        } else {
#pragma unroll
            for (int i = 0; i < 16; i++) {
                if (((key[i] - umin) >> shift) == b) {
                    int j = (tid + (i >> 2) * 256) * 4 + (i & 3);
                    unsigned long long k2 = ((unsigned long long)key[i] << 32) | (unsigned)j;
                    if (k2 > last && k2 < best) best = k2;
                }
            }
        }
#pragma unroll
        for (int off = 16; off; off >>= 1) {
            unsigned long long o = __shfl_down_sync(0xffffffffu, best, off);
            if (o < best) best = o;
        }
        if (lane == 0) wred[warp] = best;
        __syncthreads();
        if (tid == 0) {
            unsigned long long bb = wred[0];
#pragma unroll
            for (int w = 1; w < 8; w++) if (wred[w] < bb) bb = wred[w];
            orow[obase + t] = (int)(bb & 0xffffffffu);
            s_last = bb;
        }
        __syncthreads();
    }
}

// ---------------- weight pack ----------------
__global__ void wpack_k(const float* __restrict__ w, int C, int O, float* __restrict__ wp)
{
    int i = blockIdx.x * blockDim.x + threadIdx.x;
    if (i >= O * C) return;
    int o = i / C, c = i - o * C;
    float wa = w[o * 2 * C + c];
    wp[o * C + c] = wa;
    wp[(O + o) * C + c] = w[o * 2 * C + C + c] - wa;
}

// ---------------- edge gather + max + BN + leaky ----------------
__global__ void combine_k(const float* __restrict__ qp, int O,
                          const int* __restrict__ idx,
                          const float* __restrict__ sv, const float* __restrict__ bv,
                          float* __restrict__ out, int ldo)
{
    __shared__ int nb[20];
    int r = blockIdx.x;
    int base = (r >> 12) << 12;
    int tid = threadIdx.x;
    int ldq = 2 * O;
    if (tid < 20) nb[tid] = idx[(long)r * 20 + tid];
    __syncthreads();
    for (int o = tid; o < O; o += blockDim.x) {
        float m = -FLT_MAX;
#pragma unroll
        for (int kk = 0; kk < 20; kk++)
            m = fmaxf(m, qp[(long)(base + nb[kk]) * ldq + o]);
        float v = sv[o] * (m + qp[(long)r * ldq + O + o]) + bv[o];
        out[(long)r * ldo + o] = lrelu(v);
    }
}

// ---------------- global max over N (two-pass) ----------------
__global__ void gmax1_k(const float* __restrict__ emb, float* __restrict__ part)
{
    int b = blockIdx.x >> 4, sp = blockIdx.x & 15;
    int o = blockIdx.y * 256 + threadIdx.x;
    const float* e = emb + ((long)b * 4096 + (long)sp * 256) * 1024 + o;
    float m = -FLT_MAX;
    for (int n = 0; n < 256; n++) m = fmaxf(m, e[(long)n * 1024]);
    part[(long)blockIdx.x * 1024 + o] = m;
}
__global__ void gmax2_k(const float* __restrict__ part, float* __restrict__ glob)
{
    int b = blockIdx.x; int o = blockIdx.y * 256 + threadIdx.x;
    float m = -FLT_MAX;
    for (int sp = 0; sp < 16; sp++) m = fmaxf(m, part[(long)(b * 16 + sp) * 1024 + o]);
    glob[(long)b * 1024 + o] = m;
}

// ---------------- host ----------------
static void set_smem_attrs()
{
    cudaFuncSetAttribute(gemm_cp<0,0>, cudaFuncAttributeMaxDynamicSharedMemorySize, SMEM_DYN);
    cudaFuncSetAttribute(gemm_cp<1,0>, cudaFuncAttributeMaxDynamicSharedMemorySize, SMEM_DYN);
    cudaFuncSetAttribute(gemm_cp<2,1>, cudaFuncAttributeMaxDynamicSharedMemorySize, SMEM_DYN);
    cudaFuncSetAttribute(gemm_cp<3,0>, cudaFuncAttributeMaxDynamicSharedMemorySize, SMEM_DYN);
    cudaFuncSetAttribute(gemm_cp<4,0>, cudaFuncAttributeMaxDynamicSharedMemorySize, SMEM_DYN);
}

extern "C" void kernel_launch(void* const* d_in, const int* in_sizes, int n_in,
                              void* d_out, int out_size)
{
    (void)in_sizes; (void)n_in; (void)out_size;
    const float* xyz = (const float*)d_in[0];
    const float* w1 = (const float*)d_in[2];  const float* s1 = (const float*)d_in[3];  const float* b1 = (const float*)d_in[4];
    const float* w2 = (const float*)d_in[5];  const float* s2 = (const float*)d_in[6];  const float* b2 = (const float*)d_in[7];
    const float* w3 = (const float*)d_in[8];  const float* s3 = (const float*)d_in[9];  const float* b3 = (const float*)d_in[10];
    const float* w4 = (const float*)d_in[11]; const float* s4 = (const float*)d_in[12]; const float* b4 = (const float*)d_in[13];
    const float* wf = (const float*)d_in[14]; const float* sf = (const float*)d_in[15]; const float* bf = (const float*)d_in[16];
    const float* we = (const float*)d_in[17]; const float* se = (const float*)d_in[18]; const float* be = (const float*)d_in[19];
    const float* wh1 = (const float*)d_in[20]; const float* sh1 = (const float*)d_in[21]; const float* bh1 = (const float*)d_in[22];
    const float* wh2 = (const float*)d_in[23]; const float* sh2 = (const float*)d_in[24]; const float* bh2 = (const float*)d_in[25];
    const float* wh3 = (const float*)d_in[26]; const float* bh3 = (const float*)d_in[27];
    float* out = (float*)d_out;

    float *gd, *gcat, *gqp, *gx2, *glocal, *gemb, *gpart, *gglob, *ggh, *gh1, *gh2, *gwp;
    unsigned *gahl, *gbhl;
    int *gidx;
    cudaGetSymbolAddress((void**)&gd, g_d);
    cudaGetSymbolAddress((void**)&gcat, g_cat);
    cudaGetSymbolAddress((void**)&gqp, g_qp);
    cudaGetSymbolAddress((void**)&gx2, g_x2);
    cudaGetSymbolAddress((void**)&gidx, g_idx);
    cudaGetSymbolAddress((void**)&glocal, g_local);
    cudaGetSymbolAddress((void**)&gemb, g_emb);
    cudaGetSymbolAddress((void**)&gpart, g_part);
    cudaGetSymbolAddress((void**)&gglob, g_glob);
    cudaGetSymbolAddress((void**)&ggh, g_gh);
    cudaGetSymbolAddress((void**)&gh1, g_h1);
    cudaGetSymbolAddress((void**)&gh2, g_h2);
    cudaGetSymbolAddress((void**)&gwp, g_wp);
    cudaGetSymbolAddress((void**)&gahl, g_ahl);
    cudaGetSymbolAddress((void**)&gbhl, g_bhl);

    set_smem_attrs();

    const int B = 4, N = 4096, M = B * N;

    auto conv_act = [&](const float* src, int ld, int C, int K16) {
        conv_k<<<M, 256>>>(src, ld, M, C, K16, gahl);
    };
    auto conv_wt = [&](const float* src, int ld, int rows, int rowspad, int C, int K16) {
        conv_k<<<rowspad, 256>>>(src, ld, rows, C, K16, gbhl);
    };

    auto edge_layer = [&](const float* X, int ldx, int C,
                          const float* w, const float* sv, const float* bv,
                          int O, float* outCol) {
        int K16 = (C + 15) & ~15;
        conv_act(X, ldx, C, K16);
        wpack_k<<<(O * C + 255) / 256, 256>>>(w, C, O, gwp);
        conv_wt(gwp, C, 2 * O, 2 * O, C, K16);
        sqnorm_k<<<M / 8, 256>>>(X, ldx, C, gx2);
        {
            int T = N / 128;
            dim3 grid(T * (T + 1) / 2, 1, B);
            gemm_cp<2,1><<<grid, 256, SMEM_DYN>>>(
                gahl, (long)N * K16, gahl, (long)N * K16, K16, K16,
                gd, N, (long)N * N, N, K16, N, nullptr, nullptr, gx2, N);
        }
        topk_k<<<M, 256>>>(gd, gidx);
        {
            dim3 grid((2 * O) / 128, M / 128, 1);
            gemm_cp<0,0><<<grid, 256, SMEM_DYN>>>(
                gahl, 0, gbhl, 0, K16, K16,
                gqp, 2 * O, 0, M, K16, 2 * O, nullptr, nullptr, nullptr, 0);
        }
        combine_k<<<M, 128>>>(gqp, O, gidx, sv, bv, outCol, 512);
    };

    edge_layer(xyz,        3,   3,   w1, s1, b1, 64,  gcat + 0);
    edge_layer(gcat + 0,   512, 64,  w2, s2, b2, 64,  gcat + 64);
    edge_layer(gcat + 64,  512, 64,  w3, s3, b3, 128, gcat + 128);
    edge_layer(gcat + 128, 512, 128, w4, s4, b4, 256, gcat + 256);

    conv_act(gcat, 512, 512, 512);
    conv_wt(wf, 512, 512, 512, 512, 512);
    { dim3 g(512 / 128, M / 128); gemm_cp<1,0><<<g, 256, SMEM_DYN>>>(
        gahl, 0, gbhl, 0, 512, 512, glocal, 512, 0, M, 512, 512, sf, bf, nullptr, 0); }

    conv_act(glocal, 512, 512, 512);
    conv_wt(we, 512, 1024, 1024, 512, 512);
    { dim3 g(1024 / 128, M / 128); gemm_cp<1,0><<<g, 256, SMEM_DYN>>>(
        gahl, 0, gbhl, 0, 512, 512, gemb, 1024, 0, M, 512, 1024, se, be, nullptr, 0); }

    { dim3 g1(64, 4); gmax1_k<<<g1, 256>>>(gemb, gpart); }
    { dim3 g2(4, 4);  gmax2_k<<<g2, 256>>>(gpart, gglob); }

    { dim3 g(2, 1); gemm_t<0><<<g, 256>>>(gglob, 1024, wh1 + 512, 1536, ggh, 256, B, 1024, 256); }

    // h1: gahl still holds converted glocal (K16=512)
    conv_wt(wh1, 1536, 256, 256, 512, 512);
    { dim3 g(256 / 128, M / 128); gemm_cp<3,0><<<g, 256, SMEM_DYN>>>(
        gahl, 0, gbhl, 0, 512, 512, gh1, 256, 0, M, 512, 256, sh1, bh1, ggh, 256); }

    conv_act(gh1, 256, 256, 256);
    conv_wt(wh2, 256, 256, 256, 256, 256);
    { dim3 g(256 / 128, M / 128); gemm_cp<1,0><<<g, 256, SMEM_DYN>>>(
        gahl, 0, gbhl, 0, 256, 256, gh2, 256, 0, M, 256, 256, sh2, bh2, nullptr, 0); }

    conv_act(gh2, 256, 256, 256);
    conv_wt(wh3, 256, 50, 128, 256, 256);
    { dim3 g(1, M / 128); gemm_cp<4,0><<<g, 256, SMEM_DYN>>>(
        gahl, 0, gbhl, 0, 256, 256, out, 50, 0, M, 256, 50, nullptr, bh3, nullptr, 0); }
}

// round 14
// speedup vs baseline: 1.0446x; 1.0446x over previous
#include <cuda_runtime.h>
#include <cuda_fp16.h>
#include <cuda_bf16.h>
#include <cfloat>

#define LEAKF 0.2f
#define SCALEF 256.0f
#define UNSCALE (1.0f / 65536.0f)
#define PLANE (128 * 16)            // words per matrix per stage (row = 16 words)
#define PLANEB (PLANE * 4)          // 8192 B
#define STAGEB (2 * PLANEB)         // 16384 B (A + B)
#define SMEM_DYN (2 * STAGEB)       // 32768 B double-buffered

// ---------------- device scratch (no allocation allowed) ----------------
__device__ float g_d[4L * 4096 * 4096];   // 256 MB distance matrices
__device__ float g_qp[16384L * 512];
__device__ float g_x2[16384];
__device__ int   g_idx[16384L * 20];
__device__ float g_emb[16384L * 1024];
__device__ float g_part[64L * 1024];
__device__ float g_glob[4L * 1024];
__device__ float g_gh[4L * 256];
__device__ float g_wp[512 * 128];
__device__ unsigned g_ahlx[16384L * 256];  // per-layer X halves (K16 = C16 of consumer)
__device__ unsigned g_ahl[16384L * 512];   // 512-wide concat halves (wf input)
__device__ unsigned g_ahl2[16384L * 512];  // glocal halves / later gh2 halves
__device__ unsigned g_bhl[1024L * 512];    // weight halves

__device__ __forceinline__ float lrelu(float v) { return v > 0.f ? v : LEAKF * v; }

__device__ __forceinline__ unsigned f2tf32(float v) {
    unsigned r;
    asm("cvt.rna.tf32.f32 %0, %1;" : "=r"(r) : "f"(v));
    return r;
}

// pack a pair of fp32 values (already activated) into scaled fp16 hi/lo words
__device__ __forceinline__ void pack_pair(float v0, float v1, unsigned& hi, unsigned& lo)
{
    float w0 = v0 * SCALEF, w1 = v1 * SCALEF;
    __half a0 = __float2half_rn(w0);
    __half a1 = __float2half_rn(w0 - __half2float(a0));
    __half b0 = __float2half_rn(w1);
    __half b1 = __float2half_rn(w1 - __half2float(b0));
    hi = ((unsigned)__half_as_ushort(b0) << 16) | __half_as_ushort(a0);
    lo = ((unsigned)__half_as_ushort(b1) << 16) | __half_as_ushort(a1);
}
// word position of pair q within a row of K16 words (hi at ret, lo at ret+2)
__device__ __forceinline__ int pair_pos(int q)
{
    int chunk = q >> 3, c = q & 7;
    int g = c >> 2, p = c & 3;
    return chunk * 16 + p * 4 + g;
}

__device__ __forceinline__ void cpasync16(unsigned saddr, const void* g) {
    asm volatile("cp.async.ca.shared.global [%0], [%1], 16;" :: "r"(saddr), "l"(g));
}
__device__ __forceinline__ void cpcommit() { asm volatile("cp.async.commit_group;"); }
template<int N>
__device__ __forceinline__ void cpwait() { asm volatile("cp.async.wait_group %0;" :: "n"(N)); }

// ---------------- fp16 hi/lo pre-decomposition (xyz + weights) ----------
__global__ void conv_k(const float* __restrict__ src, int ld, int rows, int C,
                       int K16, unsigned* __restrict__ ohl)
{
    int r = blockIdx.x;
    long rowbase = (long)r * K16;
    for (int q = threadIdx.x; q < K16 / 2; q += blockDim.x) {
        int k0 = 2 * q;
        float v0 = (r < rows && k0 < C) ? src[(long)r * ld + k0] : 0.f;
        float v1 = (r < rows && k0 + 1 < C) ? src[(long)r * ld + k0 + 1] : 0.f;
        unsigned hi, lo;
        pack_pair(v0, v1, hi, lo);
        int pos = pair_pos(q);
        ohl[rowbase + pos] = hi;
        ohl[rowbase + pos + 2] = lo;
    }
}

// ---------------- 128x128 fp16x2 MMA GEMM (m16n8k16), cp.async double-buffered ----
// MODE 0: Y = acc
// MODE 1: Y = leaky(acc*s[n] + b[n])
// MODE 2: Y = x2[m] + x2[n] - 2*acc  (SYM=1: upper-tri tiles, mirrored writes)
// MODE 3: Y = leaky(s[n]*(acc + aux[(m>>12)*auxS + n]) + b[n])
// MODE 4: Y = acc + b[n]
// FUSE 0: write fp32 Y.  FUSE 1: write ONLY packed fp16 hi/lo pairs to Yh (k16o).
template<int MODE, int SYM, int FUSE>
__global__ __launch_bounds__(256, 2)
void gemm_cp(const unsigned* __restrict__ Ahl, long abs_,
             const unsigned* __restrict__ Bhl, long bbs,
             int lda, int ldb,
             float* __restrict__ Y, int ldy, long ybs,
             int M, int K16, int NO,
             const float* __restrict__ sv, const float* __restrict__ bv,
             const float* __restrict__ aux, int auxS,
             unsigned* __restrict__ Yh, int k16o)
{
    extern __shared__ unsigned smd[];
    unsigned sb32 = (unsigned)__cvta_generic_to_shared(smd);

    int z = blockIdx.z;
    const unsigned* Ag = Ahl + (long)z * abs_;
    const unsigned* Bg = Bhl + (long)z * bbs;
    float* Yb = Y + (long)z * ybs;

    int row0, col0;
    if (SYM) {
        int T = (M + 127) >> 7;
        int t = blockIdx.x;
        float ff = (float)(2 * T + 1);
        int bi = (int)((ff - sqrtf(ff * ff - 8.f * (float)t)) * 0.5f);
        while ((bi + 1) * T - ((bi + 1) * bi) / 2 <= t) bi++;
        while (bi * T - (bi * (bi - 1)) / 2 > t) bi--;
        int bj = bi + (t - (bi * T - (bi * (bi - 1)) / 2));
        row0 = bi << 7;
        col0 = bj << 7;
    } else {
        row0 = blockIdx.y * 128;
        col0 = blockIdx.x * 128;
    }

    int tid = threadIdx.x;
    int lane = tid & 31, wid = tid >> 5;
    int wm = wid & 3, wn = wid >> 2;
    int grp = lane >> 2, tig = lane & 3;

    float acc[2][8][4];
#pragma unroll
    for (int h = 0; h < 2; h++)
#pragma unroll
        for (int j = 0; j < 8; j++)
#pragma unroll
            for (int c = 0; c < 4; c++) acc[h][j][c] = 0.f;

    int nch = K16 >> 4;

    auto load_stage = [&](int stage, int ch) {
        unsigned base = sb32 + stage * STAGEB;
#pragma unroll
        for (int v = 0; v < 2; v++) {
            int qlin = tid + v * 256;
            int row = qlin >> 2, q = qlin & 3;
            unsigned soff = (unsigned)(row * 16 + q * 4) * 4u;
            long goa = (long)(row0 + row) * lda + (long)ch * 16 + q * 4;
            long gob = (long)(col0 + row) * ldb + (long)ch * 16 + q * 4;
            cpasync16(base + soff,          Ag + goa);
            cpasync16(base + PLANEB + soff, Bg + gob);
        }
        cpcommit();
    };

    load_stage(0, 0);

    for (int ch = 0; ch < nch; ch++) {
        int cur = ch & 1;
        if (ch + 1 < nch) load_stage(cur ^ 1, ch + 1);
        if (ch + 1 < nch) cpwait<1>(); else cpwait<0>();
        __syncthreads();

        const unsigned* As = smd + cur * 2 * PLANE;
        const unsigned* Bs = As + PLANE;

        unsigned ah[2][4], al[2][4];
#pragma unroll
        for (int h = 0; h < 2; h++) {
            int r0 = wm * 32 + h * 16 + grp;
            uint4 pa0 = *(const uint4*)&As[r0 * 16 + tig * 4];
            uint4 pa1 = *(const uint4*)&As[(r0 + 8) * 16 + tig * 4];
            ah[h][0] = pa0.x; ah[h][1] = pa1.x; ah[h][2] = pa0.y; ah[h][3] = pa1.y;
            al[h][0] = pa0.z; al[h][1] = pa1.z; al[h][2] = pa0.w; al[h][3] = pa1.w;
        }
#pragma unroll
        for (int j = 0; j < 8; j++) {
            int rb = wn * 64 + j * 8 + grp;
            uint4 pb = *(const uint4*)&Bs[rb * 16 + tig * 4];
            unsigned bh0 = pb.x, bh1 = pb.y, bl0 = pb.z, bl1 = pb.w;
#pragma unroll
            for (int h = 0; h < 2; h++) {
                asm volatile(
                    "mma.sync.aligned.m16n8k16.row.col.f32.f16.f16.f32 "
                    "{%0,%1,%2,%3}, {%4,%5,%6,%7}, {%8,%9}, {%0,%1,%2,%3};"
                    : "+f"(acc[h][j][0]), "+f"(acc[h][j][1]),
                      "+f"(acc[h][j][2]), "+f"(acc[h][j][3])
                    : "r"(al[h][0]), "r"(al[h][1]), "r"(al[h][2]), "r"(al[h][3]),
                      "r"(bh0), "r"(bh1));
                asm volatile(
                    "mma.sync.aligned.m16n8k16.row.col.f32.f16.f16.f32 "
                    "{%0,%1,%2,%3}, {%4,%5,%6,%7}, {%8,%9}, {%0,%1,%2,%3};"
                    : "+f"(acc[h][j][0]), "+f"(acc[h][j][1]),
                      "+f"(acc[h][j][2]), "+f"(acc[h][j][3])
                    : "r"(ah[h][0]), "r"(ah[h][1]), "r"(ah[h][2]), "r"(ah[h][3]),
                      "r"(bl0), "r"(bl1));
                asm volatile(
                    "mma.sync.aligned.m16n8k16.row.col.f32.f16.f16.f32 "
                    "{%0,%1,%2,%3}, {%4,%5,%6,%7}, {%8,%9}, {%0,%1,%2,%3};"
                    : "+f"(acc[h][j][0]), "+f"(acc[h][j][1]),
                      "+f"(acc[h][j][2]), "+f"(acc[h][j][3])
                    : "r"(ah[h][0]), "r"(ah[h][1]), "r"(ah[h][2]), "r"(ah[h][3]),
                      "r"(bh0), "r"(bh1));
            }
        }
        __syncthreads();
    }

#pragma unroll
    for (int h = 0; h < 2; h++) {
        int r0 = row0 + wm * 32 + h * 16 + grp;
#pragma unroll
        for (int j = 0; j < 8; j++) {
            int cb = col0 + wn * 64 + j * 8 + 2 * tig;
#pragma unroll
            for (int half = 0; half < 2; half++) {
                int gm = r0 + half * 8;
                if (gm >= M) continue;
                float vv[2];
#pragma unroll
                for (int cc = 0; cc < 2; cc++) {
                    int gn = cb + cc;
                    float v = acc[h][j][half * 2 + cc] * UNSCALE;
                    if (MODE == 1) v = lrelu(v * sv[gn] + bv[gn]);
                    else if (MODE == 2) {
                        const float* x2 = aux + (long)z * auxS;
                        v = x2[gm] + x2[gn] - 2.f * v;
                    } else if (MODE == 3) {
                        int bb = gm >> 12;
                        v = lrelu(sv[gn] * (v + aux[bb * auxS + gn]) + bv[gn]);
                    } else if (MODE == 4) v = v + bv[gn];
                    vv[cc] = v;
                    if (FUSE == 0 && gn < NO) {
                        Yb[(long)gm * ldy + gn] = v;
                        if (SYM) Yb[(long)gn * ldy + gm] = v;
                    }
                }
                if (FUSE == 1 && cb + 1 < NO) {
                    unsigned hi, lo;
                    pack_pair(vv[0], vv[1], hi, lo);
                    int pos = pair_pos(cb >> 1);
                    Yh[(long)gm * k16o + pos] = hi;
                    Yh[(long)gm * k16o + pos + 2] = lo;
                }
            }
        }
    }
}

// ---------------- scalar-load 3xTF32 GEMM (tiny 4x256 GEMM only) ------
template<int MODE>
__global__ __launch_bounds__(256, 2)
void gemm_t(const float* __restrict__ X, int ldx,
            const float* __restrict__ W, int ldw,
            float* __restrict__ Y, int ldy,
            int M, int K, int NO)
{
    __shared__ unsigned Ah[128 * 20];
    __shared__ unsigned Bh[128 * 20];
    __shared__ unsigned Al[128 * 20];
    __shared__ unsigned Bl[128 * 20];
    const int SPD = 20;

    int row0 = blockIdx.y * 128;
    int col0 = blockIdx.x * 128;
    int tid = threadIdx.x;
    int lane = tid & 31, wid = tid >> 5;
    int wm = wid & 3, wn = wid >> 2;
    int grp = lane >> 2, tig = lane & 3;

    float acc[2][8][4];
#pragma unroll
    for (int h = 0; h < 2; h++)
#pragma unroll
        for (int j = 0; j < 8; j++)
#pragma unroll
            for (int c = 0; c < 4; c++) acc[h][j][c] = 0.f;

    int nchunks = (K + 15) >> 4;
    for (int ch = 0; ch < nchunks; ch++) {
        int k0 = ch << 4;
#pragma unroll
        for (int i = 0; i < 8; i++) {
            int li = tid * 8 + i;
            int rrow = li >> 4, rcol = li & 15;
            int gk = k0 + rcol;
            int gm = row0 + rrow;
            float va = (gm < M && gk < K) ? X[(long)gm * ldx + gk] : 0.f;
            unsigned vah = f2tf32(va);
            Ah[rrow * SPD + rcol] = vah;
            Al[rrow * SPD + rcol] = f2tf32(va - __uint_as_float(vah));
            int gn = col0 + rrow;
            float vb = (gn < NO && gk < K) ? W[(long)gn * ldw + gk] : 0.f;
            unsigned vbh = f2tf32(vb);
            Bh[rrow * SPD + rcol] = vbh;
            Bl[rrow * SPD + rcol] = f2tf32(vb - __uint_as_float(vbh));
        }
        __syncthreads();
#pragma unroll
        for (int ks = 0; ks < 16; ks += 8) {
            unsigned ah[2][4], al[2][4];
#pragma unroll
            for (int h = 0; h < 2; h++) {
                int mb = wm * 32 + h * 16;
                int i0 = (mb + grp) * SPD + ks + tig;
                int i1 = (mb + grp + 8) * SPD + ks + tig;
                ah[h][0] = Ah[i0]; ah[h][1] = Ah[i1];
                ah[h][2] = Ah[i0 + 4]; ah[h][3] = Ah[i1 + 4];
                al[h][0] = Al[i0]; al[h][1] = Al[i1];
                al[h][2] = Al[i0 + 4]; al[h][3] = Al[i1 + 4];
            }
#pragma unroll
            for (int j = 0; j < 8; j++) {
                int nb = wn * 64 + j * 8;
                int ib = (nb + grp) * SPD + ks + tig;
                unsigned bh0 = Bh[ib], bh1 = Bh[ib + 4];
                unsigned bl0 = Bl[ib], bl1 = Bl[ib + 4];
#pragma unroll
                for (int h = 0; h < 2; h++) {
                    asm volatile(
                        "mma.sync.aligned.m16n8k8.row.col.f32.tf32.tf32.f32 "
                        "{%0,%1,%2,%3}, {%4,%5,%6,%7}, {%8,%9}, {%0,%1,%2,%3};"
                        : "+f"(acc[h][j][0]), "+f"(acc[h][j][1]),
                          "+f"(acc[h][j][2]), "+f"(acc[h][j][3])
                        : "r"(al[h][0]), "r"(al[h][1]), "r"(al[h][2]), "r"(al[h][3]),
                          "r"(bh0), "r"(bh1));
                    asm volatile(
                        "mma.sync.aligned.m16n8k8.row.col.f32.tf32.tf32.f32 "
                        "{%0,%1,%2,%3}, {%4,%5,%6,%7}, {%8,%9}, {%0,%1,%2,%3};"
                        : "+f"(acc[h][j][0]), "+f"(acc[h][j][1]),
                          "+f"(acc[h][j][2]), "+f"(acc[h][j][3])
                        : "r"(ah[h][0]), "r"(ah[h][1]), "r"(ah[h][2]), "r"(ah[h][3]),
                          "r"(bl0), "r"(bl1));
                    asm volatile(
                        "mma.sync.aligned.m16n8k8.row.col.f32.tf32.tf32.f32 "
                        "{%0,%1,%2,%3}, {%4,%5,%6,%7}, {%8,%9}, {%0,%1,%2,%3};"
                        : "+f"(acc[h][j][0]), "+f"(acc[h][j][1]),
                          "+f"(acc[h][j][2]), "+f"(acc[h][j][3])
                        : "r"(ah[h][0]), "r"(ah[h][1]), "r"(ah[h][2]), "r"(ah[h][3]),
                          "r"(bh0), "r"(bh1));
                }
            }
        }
        __syncthreads();
    }
#pragma unroll
    for (int h = 0; h < 2; h++) {
        int r0 = row0 + wm * 32 + h * 16 + grp;
#pragma unroll
        for (int j = 0; j < 8; j++) {
            int cb = col0 + wn * 64 + j * 8 + 2 * tig;
#pragma unroll
            for (int half = 0; half < 2; half++) {
                int gm = r0 + half * 8;
                if (gm >= M) continue;
#pragma unroll
                for (int cc = 0; cc < 2; cc++) {
                    int gn = cb + cc;
                    if (gn >= NO) continue;
                    Y[(long)gm * ldy + gn] = acc[h][j][half * 2 + cc];
                }
            }
        }
    }
}

// ---------------- squared norms (warp per row; xyz only) ----------------
__global__ void sqnorm_k(const float* __restrict__ X, int ldx, int C, float* __restrict__ x2)
{
    int warp = (blockIdx.x * blockDim.x + threadIdx.x) >> 5;
    int lane = threadIdx.x & 31;
    if (warp >= 16384) return;
    const float* xr = X + (long)warp * ldx;
    float s = 0.f;
    for (int c = lane; c < C; c += 32) { float v = xr[c]; s = fmaf(v, v, s); }
#pragma unroll
    for (int off = 16; off; off >>= 1) s += __shfl_down_sync(0xffffffffu, s, off);
    if (lane == 0) x2[warp] = s;
}

// ---------------- top-20 smallest: single-pass 2048-bin radix select (round-9) -----
__global__ __launch_bounds__(256) void topk_k(const float* __restrict__ D, int* __restrict__ idx)
{
    __shared__ unsigned skey[4096];
    __shared__ int hist[2048];
    __shared__ int cand[4096];
    __shared__ int wsum[8];
    __shared__ int sb, sexcl, socnt, sccnt;
    __shared__ unsigned long long wred[8];
    __shared__ unsigned long long s_last;

    long r = blockIdx.x;
    const float4* drow = (const float4*)(D + r * 4096);
    int* orow = idx + r * 20;
    int tid = threadIdx.x;
    int lane = tid & 31, warp = tid >> 5;

#pragma unroll
    for (int i = 0; i < 8; i++) hist[tid + i * 256] = 0;
    if (tid == 0) { socnt = 0; sccnt = 0; s_last = 0ull; }
    __syncthreads();

#pragma unroll
    for (int v = 0; v < 4; v++) {
        int j4 = tid + v * 256;
        float4 d4 = drow[j4];
        unsigned k0 = __float_as_uint(fmaxf(d4.x, 0.f));
        unsigned k1 = __float_as_uint(fmaxf(d4.y, 0.f));
        unsigned k2 = __float_as_uint(fmaxf(d4.z, 0.f));
        unsigned k3 = __float_as_uint(fmaxf(d4.w, 0.f));
        skey[j4 * 4 + 0] = k0; skey[j4 * 4 + 1] = k1;
        skey[j4 * 4 + 2] = k2; skey[j4 * 4 + 3] = k3;
        atomicAdd(&hist[k0 >> 21], 1);
        atomicAdd(&hist[k1 >> 21], 1);
        atomicAdd(&hist[k2 >> 21], 1);
        atomicAdd(&hist[k3 >> 21], 1);
    }
    __syncthreads();

    int csum[8];
    int tot = 0;
#pragma unroll
    for (int i = 0; i < 8; i++) { tot += hist[tid * 8 + i]; csum[i] = tot; }
    int sc = tot;
#pragma unroll
    for (int off = 1; off < 32; off <<= 1) {
        int t = __shfl_up_sync(0xffffffffu, sc, off);
        if (lane >= off) sc += t;
    }
    if (lane == 31) wsum[warp] = sc;
    __syncthreads();
    if (tid < 8) {
        int w = wsum[tid];
#pragma unroll
        for (int off = 1; off < 8; off <<= 1) {
            int t = __shfl_up_sync(0xffu, w, off);
            if (tid >= off) w += t;
        }
        wsum[tid] = w;
    }
    __syncthreads();
    int base = sc - tot + (warp ? wsum[warp - 1] : 0);

    if (base < 20 && base + tot >= 20) {
#pragma unroll
        for (int i = 0; i < 8; i++) {
            int incl = base + csum[i];
            int excl = incl - hist[tid * 8 + i];
            if (excl < 20 && incl >= 20) { sb = tid * 8 + i; sexcl = excl; }
        }
    }
    __syncthreads();
    unsigned b = (unsigned)sb;
    int need = 20 - sexcl;

    for (int j = tid; j < 4096; j += 256) {
        unsigned bin = skey[j] >> 21;
        if (bin < b) {
            int p = atomicAdd(&socnt, 1);
            orow[p] = j;
        } else if (bin == b) {
            int p = atomicAdd(&sccnt, 1);
            cand[p] = j;
        }
    }
    __syncthreads();
    int m = sccnt;
    int obase = socnt;

    for (int t = 0; t < need; t++) {
        unsigned long long last = s_last;
        unsigned long long best = ~0ull;
        for (int c = tid; c < m; c += 256) {
            int j = cand[c];
            unsigned long long key = ((unsigned long long)skey[j] << 32) | (unsigned)j;
            if (key > last && key < best) best = key;
        }
#pragma unroll
        for (int off = 16; off; off >>= 1) {
            unsigned long long o = __shfl_down_sync(0xffffffffu, best, off);
            if (o < best) best = o;
        }
        if (lane == 0) wred[warp] = best;
        __syncthreads();
        if (tid == 0) {
            unsigned long long bb = wred[0];
#pragma unroll
            for (int w = 1; w < 8; w++) if (wred[w] < bb) bb = wred[w];
            orow[obase + t] = (int)(bb & 0xffffffffu);
            s_last = bb;
        }
        __syncthreads();
    }
}

// ---------------- weight pack ----------------
__global__ void wpack_k(const float* __restrict__ w, int C, int O, float* __restrict__ wp)
{
    int i = blockIdx.x * blockDim.x + threadIdx.x;
    if (i >= O * C) return;
    int o = i / C, c = i - o * C;
    float wa = w[o * 2 * C + c];
    wp[o * C + c] = wa;
    wp[(O + o) * C + c] = w[o * 2 * C + C + c] - wa;
}

// ---------------- edge gather + max + BN + leaky, fused conversion + x2 ----------
// One block per row r. Computes v_o, writes:
//  - ahlx: packed halves, row stride k16x (= O) — next layer's X
//  - ahl512: packed halves into the 512-wide concat at pair offset qoff
//  - x2out[r] = sum_o v_o^2   (next layer's squared norms)
__global__ __launch_bounds__(128)
void combine_k(const float* __restrict__ qp, int O,
               const int* __restrict__ idx,
               const float* __restrict__ sv, const float* __restrict__ bv,
               unsigned* __restrict__ ahlx, int k16x,
               unsigned* __restrict__ ahl512, int qoff,
               float* __restrict__ x2out)
{
    __shared__ int nb[20];
    __shared__ float rss[128];
    int r = blockIdx.x;
    int base = (r >> 12) << 12;
    int tid = threadIdx.x;
    int ldq = 2 * O;
    if (tid < 20) nb[tid] = idx[(long)r * 20 + tid];
    __syncthreads();

    float ss = 0.f;
    for (int q = tid; 2 * q < O; q += 128) {
        float v[2];
#pragma unroll
        for (int e = 0; e < 2; e++) {
            int o = 2 * q + e;
            float m = -FLT_MAX;
#pragma unroll
            for (int kk = 0; kk < 20; kk++)
                m = fmaxf(m, qp[(long)(base + nb[kk]) * ldq + o]);
            float t = sv[o] * (m + qp[(long)r * ldq + O + o]) + bv[o];
            v[e] = lrelu(t);
            ss += v[e] * v[e];
        }
        unsigned hi, lo;
        pack_pair(v[0], v[1], hi, lo);
        int pos = pair_pos(q);
        ahlx[(long)r * k16x + pos] = hi;
        ahlx[(long)r * k16x + pos + 2] = lo;
        int pos5 = pair_pos(qoff + q);
        ahl512[(long)r * 512 + pos5] = hi;
        ahl512[(long)r * 512 + pos5 + 2] = lo;
    }
    rss[tid] = ss;
    __syncthreads();
    for (int s = 64; s > 0; s >>= 1) {
        if (tid < s) rss[tid] += rss[tid + s];
        __syncthreads();
    }
    if (tid == 0) x2out[r] = rss[0];
}

// ---------------- global max over N (two-pass) ----------------
__global__ void gmax1_k(const float* __restrict__ emb, float* __restrict__ part)
{
    int b = blockIdx.x >> 4, sp = blockIdx.x & 15;
    int o = blockIdx.y * 256 + threadIdx.x;
    const float* e = emb + ((long)b * 4096 + (long)sp * 256) * 1024 + o;
    float m = -FLT_MAX;
    for (int n = 0; n < 256; n++) m = fmaxf(m, e[(long)n * 1024]);
    part[(long)blockIdx.x * 1024 + o] = m;
}
__global__ void gmax2_k(const float* __restrict__ part, float* __restrict__ glob)
{
    int b = blockIdx.x; int o = blockIdx.y * 256 + threadIdx.x;
    float m = -FLT_MAX;
    for (int sp = 0; sp < 16; sp++) m = fmaxf(m, part[(long)(b * 16 + sp) * 1024 + o]);
    glob[(long)b * 1024 + o] = m;
}

// ---------------- host ----------------
static void set_smem_attrs()
{
    cudaFuncSetAttribute(gemm_cp<0,0,0>, cudaFuncAttributeMaxDynamicSharedMemorySize, SMEM_DYN);
    cudaFuncSetAttribute(gemm_cp<1,0,0>, cudaFuncAttributeMaxDynamicSharedMemorySize, SMEM_DYN);
    cudaFuncSetAttribute(gemm_cp<1,0,1>, cudaFuncAttributeMaxDynamicSharedMemorySize, SMEM_DYN);
    cudaFuncSetAttribute(gemm_cp<2,1,0>, cudaFuncAttributeMaxDynamicSharedMemorySize, SMEM_DYN);
    cudaFuncSetAttribute(gemm_cp<3,0,1>, cudaFuncAttributeMaxDynamicSharedMemorySize, SMEM_DYN);
    cudaFuncSetAttribute(gemm_cp<4,0,0>, cudaFuncAttributeMaxDynamicSharedMemorySize, SMEM_DYN);
}

extern "C" void kernel_launch(void* const* d_in, const int* in_sizes, int n_in,
                              void* d_out, int out_size)
{
    (void)in_sizes; (void)n_in; (void)out_size;
    const float* xyz = (const float*)d_in[0];
    const float* w1 = (const float*)d_in[2];  const float* s1 = (const float*)d_in[3];  const float* b1 = (const float*)d_in[4];
    const float* w2 = (const float*)d_in[5];  const float* s2 = (const float*)d_in[6];  const float* b2 = (const float*)d_in[7];
    const float* w3 = (const float*)d_in[8];  const float* s3 = (const float*)d_in[9];  const float* b3 = (const float*)d_in[10];
    const float* w4 = (const float*)d_in[11]; const float* s4 = (const float*)d_in[12]; const float* b4 = (const float*)d_in[13];
    const float* wf = (const float*)d_in[14]; const float* sf = (const float*)d_in[15]; const float* bf = (const float*)d_in[16];
    const float* we = (const float*)d_in[17]; const float* se = (const float*)d_in[18]; const float* be = (const float*)d_in[19];
    const float* wh1 = (const float*)d_in[20]; const float* sh1 = (const float*)d_in[21]; const float* bh1 = (const float*)d_in[22];
    const float* wh2 = (const float*)d_in[23]; const float* sh2 = (const float*)d_in[24]; const float* bh2 = (const float*)d_in[25];
    const float* wh3 = (const float*)d_in[26]; const float* bh3 = (const float*)d_in[27];
    float* out = (float*)d_out;

    float *gd, *gqp, *gx2, *gemb, *gpart, *gglob, *ggh, *gwp;
    unsigned *gahlx, *gahl, *gahl2, *gbhl;
    int *gidx;
    cudaGetSymbolAddress((void**)&gd, g_d);
    cudaGetSymbolAddress((void**)&gqp, g_qp);
    cudaGetSymbolAddress((void**)&gx2, g_x2);
    cudaGetSymbolAddress((void**)&gidx, g_idx);
    cudaGetSymbolAddress((void**)&gemb, g_emb);
    cudaGetSymbolAddress((void**)&gpart, g_part);
    cudaGetSymbolAddress((void**)&gglob, g_glob);
    cudaGetSymbolAddress((void**)&ggh, g_gh);
    cudaGetSymbolAddress((void**)&gwp, g_wp);
    cudaGetSymbolAddress((void**)&gahlx, g_ahlx);
    cudaGetSymbolAddress((void**)&gahl, g_ahl);
    cudaGetSymbolAddress((void**)&gahl2, g_ahl2);
    cudaGetSymbolAddress((void**)&gbhl, g_bhl);

    set_smem_attrs();

    const int B = 4, N = 4096, M = B * N;

    // layer-1 input conversion + norms
    conv_k<<<M, 256>>>(xyz, 3, M, 3, 16, gahlx);
    sqnorm_k<<<M / 8, 256>>>(xyz, 3, 3, gx2);

    // one EdgeConv layer: X halves in gahlx (K16X), x2 in gx2
    auto edge_layer = [&](int K16X,
                          const float* w, const float* sv, const float* bv,
                          int O, int off512) {
        int C = K16X;  // padded (layer1 C=3 zero-padded to 16 via conv)
        wpack_k<<<(O * (C > 16 ? C : 3) + 255) / 256, 256>>>(w, (off512 == 0 ? 3 : C), O, gwp);
        conv_k<<<2 * O, 256>>>(gwp, (off512 == 0 ? 3 : C), 2 * O, (off512 == 0 ? 3 : C), K16X, gbhl);
        {
            int T = N / 128;
            dim3 grid(T * (T + 1) / 2, 1, B);
            gemm_cp<2,1,0><<<grid, 256, SMEM_DYN>>>(
                gahlx, (long)N * K16X, gahlx, (long)N * K16X, K16X, K16X,
                gd, N, (long)N * N, N, K16X, N, nullptr, nullptr, gx2, N, nullptr, 0);
        }
        topk_k<<<M, 256>>>(gd, gidx);
        {
            dim3 grid((2 * O) / 128, M / 128, 1);
            gemm_cp<0,0,0><<<grid, 256, SMEM_DYN>>>(
                gahlx, 0, gbhl, 0, K16X, K16X,
                gqp, 2 * O, 0, M, K16X, 2 * O, nullptr, nullptr, nullptr, 0, nullptr, 0);
        }
        combine_k<<<M, 128>>>(gqp, O, gidx, sv, bv, gahlx, O, gahl, off512 / 2, gx2);
    };

    edge_layer(16,  w1, s1, b1, 64,  0);
    edge_layer(64,  w2, s2, b2, 64,  64);
    edge_layer(64,  w3, s3, b3, 128, 128);
    edge_layer(128, w4, s4, b4, 256, 256);

    // x_local halves = leaky(cat*wf^T*sf+bf)  -> gahl2 (halves only)
    conv_k<<<512, 256>>>(wf, 512, 512, 512, 512, gbhl);
    { dim3 g(512 / 128, M / 128); gemm_cp<1,0,1><<<g, 256, SMEM_DYN>>>(
        gahl, 0, gbhl, 0, 512, 512, nullptr, 0, 0, M, 512, 512, sf, bf, nullptr, 0, gahl2, 512); }

    // x_emb fp32 = leaky(local*we^T*se+be)
    conv_k<<<1024, 256>>>(we, 512, 1024, 512, 512, gbhl);
    { dim3 g(1024 / 128, M / 128); gemm_cp<1,0,0><<<g, 256, SMEM_DYN>>>(
        gahl2, 0, gbhl, 0, 512, 512, gemb, 1024, 0, M, 512, 1024, se, be, nullptr, 0, nullptr, 0); }

    { dim3 g1(64, 4); gmax1_k<<<g1, 256>>>(gemb, gpart); }
    { dim3 g2(4, 4);  gmax2_k<<<g2, 256>>>(gpart, gglob); }

    { dim3 g(2, 1); gemm_t<0><<<g, 256>>>(gglob, 1024, wh1 + 512, 1536, ggh, 256, B, 1024, 256); }

    // h1 halves = leaky(sh1*(local*wh1[:, :512]^T + G) + bh1) -> gahlx (K16=256)
    conv_k<<<256, 256>>>(wh1, 1536, 256, 512, 512, gbhl);
    { dim3 g(256 / 128, M / 128); gemm_cp<3,0,1><<<g, 256, SMEM_DYN>>>(
        gahl2, 0, gbhl, 0, 512, 512, nullptr, 0, 0, M, 512, 256, sh1, bh1, ggh, 256, gahlx, 256); }

    // h2 halves = leaky(h1*wh2^T*sh2+bh2) -> gahl2 (row stride 256)
    conv_k<<<256, 256>>>(wh2, 256, 256, 256, 256, gbhl);
    { dim3 g(256 / 128, M / 128); gemm_cp<1,0,1><<<g, 256, SMEM_DYN>>>(
        gahlx, 0, gbhl, 0, 256, 256, nullptr, 0, 0, M, 256, 256, sh2, bh2, nullptr, 0, gahl2, 256); }

    // logits = h2*wh3^T + bh3   (wh3 rows padded 50 -> 128 with zeros)
    conv_k<<<128, 256>>>(wh3, 256, 50, 256, 256, gbhl);
    { dim3 g(1, M / 128); gemm_cp<4,0,0><<<g, 256, SMEM_DYN>>>(
        gahl2, 0, gbhl, 0, 256, 256, out, 50, 0, M, 256, 50, nullptr, bh3, nullptr, 0, nullptr, 0); }
}